// round 3
// baseline (speedup 1.0000x reference)
#include <cuda_runtime.h>

#define B_  2
#define S_  2048
#define D_  1024
#define H_  16
#define DH_ 64
#define M_  (B_*S_)

// Scratch for projected Q/K/V (allocation-free rule: __device__ globals)
__device__ float g_Q[M_*D_];
__device__ float g_K[M_*D_];
__device__ float g_V[M_*D_];

// ---------------------------------------------------------------------------
// Projection GEMM: C = A[4096,1024] @ W[1024,1024] + bias, z selects q/k/v.
// 128x128x16 tile, 256 threads, 8x8 microtile.
// ---------------------------------------------------------------------------
__global__ __launch_bounds__(256, 2)
void proj_gemm(const float* __restrict__ Aq, const float* __restrict__ Ak,
               const float* __restrict__ Av,
               const float* __restrict__ Wq, const float* __restrict__ Wk,
               const float* __restrict__ Wv,
               const float* __restrict__ bq, const float* __restrict__ bk,
               const float* __restrict__ bv)
{
    const int N = D_, K = D_;
    const int z = blockIdx.z;
    const float* A    = (z == 0) ? Aq : (z == 1) ? Ak : Av;
    const float* W    = (z == 0) ? Wq : (z == 1) ? Wk : Wv;
    const float* bias = (z == 0) ? bq : (z == 1) ? bk : bv;
    float* C          = (z == 0) ? g_Q : (z == 1) ? g_K : g_V;

    __shared__ float As[16][128];   // A^T tile
    __shared__ float Bs[16][128];

    const int tid  = threadIdx.x;
    const int brow = blockIdx.y * 128;
    const int bcol = blockIdx.x * 128;
    const int ry   = tid >> 4;      // 0..15
    const int rx   = tid & 15;      // 0..15

    float acc[8][8];
    #pragma unroll
    for (int i = 0; i < 8; i++)
        #pragma unroll
        for (int j = 0; j < 8; j++) acc[i][j] = 0.f;

    for (int k0 = 0; k0 < K; k0 += 16) {
        #pragma unroll
        for (int l = 0; l < 2; l++) {
            int idx = tid + l * 256;            // 0..511
            // A tile: 128 rows x 16 cols (transpose-store)
            int arow = idx >> 2;
            int ac4  = (idx & 3) << 2;
            float4 va = *(const float4*)&A[(brow + arow) * K + k0 + ac4];
            As[ac4 + 0][arow] = va.x;
            As[ac4 + 1][arow] = va.y;
            As[ac4 + 2][arow] = va.z;
            As[ac4 + 3][arow] = va.w;
            // B tile: 16 rows x 128 cols (coalesced)
            int browk = idx >> 5;
            int bc4   = (idx & 31) << 2;
            *(float4*)&Bs[browk][bc4] =
                *(const float4*)&W[(k0 + browk) * N + bcol + bc4];
        }
        __syncthreads();

        #pragma unroll
        for (int kk = 0; kk < 16; kk++) {
            float a[8], b[8];
            float4 t;
            t = *(float4*)&As[kk][ry*8];     a[0]=t.x; a[1]=t.y; a[2]=t.z; a[3]=t.w;
            t = *(float4*)&As[kk][ry*8+4];   a[4]=t.x; a[5]=t.y; a[6]=t.z; a[7]=t.w;
            t = *(float4*)&Bs[kk][rx*8];     b[0]=t.x; b[1]=t.y; b[2]=t.z; b[3]=t.w;
            t = *(float4*)&Bs[kk][rx*8+4];   b[4]=t.x; b[5]=t.y; b[6]=t.z; b[7]=t.w;
            #pragma unroll
            for (int i = 0; i < 8; i++)
                #pragma unroll
                for (int j = 0; j < 8; j++)
                    acc[i][j] = fmaf(a[i], b[j], acc[i][j]);
        }
        __syncthreads();
    }

    float bb[8];
    {
        float4 t = *(const float4*)&bias[bcol + rx*8];
        bb[0]=t.x; bb[1]=t.y; bb[2]=t.z; bb[3]=t.w;
        t = *(const float4*)&bias[bcol + rx*8 + 4];
        bb[4]=t.x; bb[5]=t.y; bb[6]=t.z; bb[7]=t.w;
    }
    #pragma unroll
    for (int i = 0; i < 8; i++) {
        int row = brow + ry*8 + i;
        float4 o0 = make_float4(acc[i][0]+bb[0], acc[i][1]+bb[1],
                                acc[i][2]+bb[2], acc[i][3]+bb[3]);
        float4 o1 = make_float4(acc[i][4]+bb[4], acc[i][5]+bb[5],
                                acc[i][6]+bb[6], acc[i][7]+bb[7]);
        *(float4*)&C[row * N + bcol + rx*8]     = o0;
        *(float4*)&C[row * N + bcol + rx*8 + 4] = o1;
    }
}

// ---------------------------------------------------------------------------
// Flash attention (fp32). One CTA = 128 q-rows of one (b,h); loops kv in 64s.
// 128 threads, 8x8 microtile. Q^T/K^T/P^T tiles XOR-swizzled in smem.
// ---------------------------------------------------------------------------
#define BM  128
#define BN  64
#define ATH 128

#define ASMEM_FLOATS (64*128 + 64*64 + 64*64 + 64*128 + 64)
#define ASMEM_BYTES  (ASMEM_FLOATS * 4)

__global__ __launch_bounds__(ATH, 2)
void flash_attn(const int* __restrict__ mask, float* __restrict__ out)
{
    extern __shared__ float sm[];
    float* Qs   = sm;               // [d][r] swizzled, stride 128
    float* Ks   = Qs + 64*128;      // [d][c] swizzled, stride 64
    float* Vs   = Ks + 64*64;       // [kv][c] natural, stride 64
    float* Ps   = Vs + 64*64;       // [kv][r] swizzled, stride 128
    float* madd = Ps + 64*128;      // [64] additive mask

    const int tid = threadIdx.x;
    const int ty  = tid >> 3;       // 0..15 -> rows
    const int tx  = tid & 7;        // 0..7  -> cols
    const int R   = ty << 3;
    const int C   = tx << 3;
    const int bh  = blockIdx.y;
    const int b   = bh >> 4;        // H_=16
    const int h   = bh & 15;
    const int q0  = blockIdx.x * BM;
    const float scale = 0.03125f;   // 1/sqrt(1024)

    const float* Qb = g_Q + (size_t)b * S_ * D_ + h * DH_;
    const float* Kb = g_K + (size_t)b * S_ * D_ + h * DH_;
    const float* Vb = g_V + (size_t)b * S_ * D_ + h * DH_;

    // Load Q tile [128 x 64] transposed + swizzled
    #pragma unroll
    for (int l = 0; l < 16; l++) {
        int idx = tid + l * ATH;            // 0..2047 float4s
        int row = idx >> 4;                 // 0..127
        int dz  = idx & 15;                 // d>>2
        float4 v = *(const float4*)&Qb[(q0 + row) * D_ + (dz << 2)];
        int blk = (((row >> 2) ^ dz) << 2) + (row & 3);
        Qs[(dz*4 + 0)*128 + blk] = v.x;
        Qs[(dz*4 + 1)*128 + blk] = v.y;
        Qs[(dz*4 + 2)*128 + blk] = v.z;
        Qs[(dz*4 + 3)*128 + blk] = v.w;
    }

    float m_i[8], l_i[8], o[8][8];
    #pragma unroll
    for (int i = 0; i < 8; i++) {
        m_i[i] = -1e30f; l_i[i] = 0.f;
        #pragma unroll
        for (int j = 0; j < 8; j++) o[i][j] = 0.f;
    }

    for (int kv0 = 0; kv0 < S_; kv0 += BN) {
        __syncthreads();   // prior PV reads of Vs/Ps done before overwrite

        // Load K (transposed+swizzled) and V (natural) tiles [64 x 64]
        #pragma unroll
        for (int l = 0; l < 8; l++) {
            int idx = tid + l * ATH;        // 0..1023 float4s
            int row = idx >> 4;             // 0..63 (kv token)
            int dz  = idx & 15;
            float4 kv4 = *(const float4*)&Kb[(kv0 + row) * D_ + (dz << 2)];
            int blk = (((row >> 2) ^ dz) << 2) + (row & 3);
            Ks[(dz*4 + 0)*64 + blk] = kv4.x;
            Ks[(dz*4 + 1)*64 + blk] = kv4.y;
            Ks[(dz*4 + 2)*64 + blk] = kv4.z;
            Ks[(dz*4 + 3)*64 + blk] = kv4.w;
            float4 vv4 = *(const float4*)&Vb[(kv0 + row) * D_ + (dz << 2)];
            *(float4*)&Vs[row*64 + (dz << 2)] = vv4;
        }
        if (tid < 64)
            madd[tid] = mask[b * S_ + kv0 + tid] ? 0.f : -1e9f;
        __syncthreads();

        // S = Q K^T  (8x8 per thread over d=64)
        float s[8][8];
        #pragma unroll
        for (int i = 0; i < 8; i++)
            #pragma unroll
            for (int j = 0; j < 8; j++) s[i][j] = 0.f;

        #pragma unroll 8
        for (int d = 0; d < 64; d++) {
            int dz = d >> 2;
            float a[8], bb[8];
            float4 t;
            t = *(float4*)&Qs[d*128 + (((2*ty  ) ^ dz) << 2)];
            a[0]=t.x; a[1]=t.y; a[2]=t.z; a[3]=t.w;
            t = *(float4*)&Qs[d*128 + (((2*ty+1) ^ dz) << 2)];
            a[4]=t.x; a[5]=t.y; a[6]=t.z; a[7]=t.w;
            t = *(float4*)&Ks[d*64  + (((2*tx  ) ^ dz) << 2)];
            bb[0]=t.x; bb[1]=t.y; bb[2]=t.z; bb[3]=t.w;
            t = *(float4*)&Ks[d*64  + (((2*tx+1) ^ dz) << 2)];
            bb[4]=t.x; bb[5]=t.y; bb[6]=t.z; bb[7]=t.w;
            #pragma unroll
            for (int i = 0; i < 8; i++)
                #pragma unroll
                for (int j = 0; j < 8; j++)
                    s[i][j] = fmaf(a[i], bb[j], s[i][j]);
        }

        float ma[8];
        #pragma unroll
        for (int j = 0; j < 8; j++) ma[j] = madd[C + j];

        // Online softmax update (row reduction across the 8-lane tx group)
        #pragma unroll
        for (int i = 0; i < 8; i++) {
            #pragma unroll
            for (int j = 0; j < 8; j++) s[i][j] = fmaf(s[i][j], scale, ma[j]);
            float mx = s[i][0];
            #pragma unroll
            for (int j = 1; j < 8; j++) mx = fmaxf(mx, s[i][j]);
            mx = fmaxf(mx, __shfl_xor_sync(0xffffffffu, mx, 1));
            mx = fmaxf(mx, __shfl_xor_sync(0xffffffffu, mx, 2));
            mx = fmaxf(mx, __shfl_xor_sync(0xffffffffu, mx, 4));
            float mn = fmaxf(m_i[i], mx);
            float al = __expf(m_i[i] - mn);
            float rs = 0.f;
            #pragma unroll
            for (int j = 0; j < 8; j++) {
                float p = __expf(s[i][j] - mn);
                s[i][j] = p;
                rs += p;
            }
            rs += __shfl_xor_sync(0xffffffffu, rs, 1);
            rs += __shfl_xor_sync(0xffffffffu, rs, 2);
            rs += __shfl_xor_sync(0xffffffffu, rs, 4);
            l_i[i] = l_i[i] * al + rs;
            m_i[i] = mn;
            #pragma unroll
            for (int j = 0; j < 8; j++) o[i][j] *= al;
            // store P transposed+swizzled: Ps[kv][r]
            int r = R + i;
            #pragma unroll
            for (int j = 0; j < 8; j++) {
                int kv = C + j;
                Ps[kv*128 + (((r >> 2) ^ (kv >> 2)) << 2) + (r & 3)] = s[i][j];
            }
        }
        __syncthreads();

        // O += P V  (8x8 per thread over kv=64)
        #pragma unroll 8
        for (int kv = 0; kv < 64; kv++) {
            int kz = kv >> 2;
            float p[8], v[8];
            float4 t;
            t = *(float4*)&Ps[kv*128 + (((2*ty  ) ^ kz) << 2)];
            p[0]=t.x; p[1]=t.y; p[2]=t.z; p[3]=t.w;
            t = *(float4*)&Ps[kv*128 + (((2*ty+1) ^ kz) << 2)];
            p[4]=t.x; p[5]=t.y; p[6]=t.z; p[7]=t.w;
            t = *(float4*)&Vs[kv*64 + C];
            v[0]=t.x; v[1]=t.y; v[2]=t.z; v[3]=t.w;
            t = *(float4*)&Vs[kv*64 + C + 4];
            v[4]=t.x; v[5]=t.y; v[6]=t.z; v[7]=t.w;
            #pragma unroll
            for (int i = 0; i < 8; i++)
                #pragma unroll
                for (int j = 0; j < 8; j++)
                    o[i][j] = fmaf(p[i], v[j], o[i][j]);
        }
    }

    // Normalize and write out[b, q0+R+i, h*64 + C + j]
    #pragma unroll
    for (int i = 0; i < 8; i++) {
        float inv = 1.f / l_i[i];
        float4 o0 = make_float4(o[i][0]*inv, o[i][1]*inv, o[i][2]*inv, o[i][3]*inv);
        float4 o1 = make_float4(o[i][4]*inv, o[i][5]*inv, o[i][6]*inv, o[i][7]*inv);
        size_t base = ((size_t)b * S_ + q0 + R + i) * D_ + h * DH_ + C;
        *(float4*)&out[base]     = o0;
        *(float4*)&out[base + 4] = o1;
    }
}

// ---------------------------------------------------------------------------
extern "C" void kernel_launch(void* const* d_in, const int* in_sizes, int n_in,
                              void* d_out, int out_size)
{
    const float* q    = (const float*)d_in[0];
    const float* k    = (const float*)d_in[1];
    const float* v    = (const float*)d_in[2];
    const int*   mask = (const int*)  d_in[3];
    const float* Wq   = (const float*)d_in[4];
    const float* bq   = (const float*)d_in[5];
    const float* Wk   = (const float*)d_in[6];
    const float* bk   = (const float*)d_in[7];
    const float* Wv   = (const float*)d_in[8];
    const float* bv   = (const float*)d_in[9];
    float* out = (float*)d_out;

    (void)in_sizes; (void)n_in; (void)out_size;

    dim3 g1(D_/128, M_/128, 3);   // 8 x 32 x 3
    proj_gemm<<<g1, 256>>>(q, k, v, Wq, Wk, Wv, bq, bk, bv);

    cudaFuncSetAttribute(flash_attn,
                         cudaFuncAttributeMaxDynamicSharedMemorySize,
                         ASMEM_BYTES);
    dim3 g2(S_/BM, B_*H_);        // 16 x 32
    flash_attn<<<g2, ATH, ASMEM_BYTES>>>(mask, out);
}